// round 12
// baseline (speedup 1.0000x reference)
#include <cuda_runtime.h>
#include <cstdint>

// ---------------------------------------------------------------------------
// CML2DWithStats, round 12: 24 warps/SM via 1-pair threads + 16-CTA cluster,
// with a host-side validated fallback to the proven cluster-8 kernel.
//
//   g_{t+1} = clamp( conv3x3( m_t, K' ) + BETA*drive ),  m = g*(1-g)
//   K' = R*(1-BETA)*(EPS*K + (1-EPS)*delta_center)
//
// Primary (cml16): cluster (16,1,1) spans a plane; CTA = 256 thr owns a
// 16-row strip; each warp-row ty owns ONE row-pair -> stats = 32 regs,
// peak ~80 regs -> __launch_bounds__(256,3): 3 CTAs/SM = 6 warps/SMSP.
// smem 36 KB/CTA. Pull-based DSMEM halo (warps 0/7, sole readers of their
// slots); cluster barrier per step.
//
// Fallback (cml8): round-10 kernel (cluster 8, 32-row strips, 2 pairs/thread,
// 2 CTAs/SM) — selected when cluster-16 attributes/occupancy are unsupported.
// ---------------------------------------------------------------------------

#define R_PARAM  3.9f
#define EPS_P    0.3f
#define BETA_P   0.15f
#define NSTEPS   15
#define CLAMP_LO 1e-4f
#define CLAMP_HI (1.0f - 1e-4f)

constexpr int W      = 256;
constexpr int NPLANE = W * 256;
constexpr long long NTOT = 16LL * 8 * NPLANE;

__device__ __forceinline__ float clampg(float v) {
    return fminf(fmaxf(v, CLAMP_LO), CLAMP_HI);
}

__device__ __forceinline__ uint32_t smem_u32(const void* p) {
    uint32_t a;
    asm("{ .reg .u64 t; cvta.to.shared.u64 t, %1; cvt.u32.u64 %0, t; }"
        : "=r"(a) : "l"(p));
    return a;
}

__device__ __forceinline__ float4 dsmem_ld4(uint32_t my_addr, uint32_t rank) {
    uint32_t ra; float4 v;
    asm volatile("mapa.shared::cluster.u32 %0, %1, %2;"
                 : "=r"(ra) : "r"(my_addr), "r"(rank));
    asm volatile("ld.shared::cluster.v4.f32 {%0, %1, %2, %3}, [%4];"
                 : "=f"(v.x), "=f"(v.y), "=f"(v.z), "=f"(v.w) : "r"(ra));
    return v;
}

#define CLUSTER_BAR()                                                       \
    do {                                                                    \
        asm volatile("barrier.cluster.arrive.aligned;" ::: "memory");       \
        asm volatile("barrier.cluster.wait.aligned;"   ::: "memory");       \
    } while (0)

// ===========================================================================
// PRIMARY: cml16 — 16-row strips, cluster 16, 3 CTAs/SM
// ===========================================================================

constexpr int P_RCTA   = 16;
constexpr int P_NSTRIP = 16;
constexpr int P_BROWS  = 18;                   // 16 own + 2 halo slots
constexpr int P_TYN    = 8;
constexpr int P_NTHR   = 32 * P_TYN;           // 256
constexpr int P_BUF    = P_BROWS * W;          // 4608 floats
constexpr int P_SMEM   = 2 * P_BUF * 4;        // 36864 B

__global__ void __launch_bounds__(P_NTHR, 3) __cluster_dims__(P_NSTRIP, 1, 1)
cml16_kernel(const float* __restrict__ drive,
             const float* __restrict__ Klocal,
             float* __restrict__ out)
{
    extern __shared__ float sm[];
    float* MB0 = sm;
    float* MB1 = sm + P_BUF;

    const int tx = threadIdx.x;
    const int ty = threadIdx.y;
    const int strip = blockIdx.x;          // cluster rank 0..15
    const int c     = blockIdx.y;
    const int b     = blockIdx.z;
    const int x4    = tx * 4;
    const int x0    = tx * 8;
    const int rbase = strip * P_RCTA;

    float kk[3][3];
    {
        const float* kc = Klocal + c * 9;
        #pragma unroll
        for (int j = 0; j < 3; ++j)
            #pragma unroll
            for (int i = 0; i < 3; ++i) {
                float v = EPS_P * kc[j * 3 + i];
                if (j == 1 && i == 1) v += (1.0f - EPS_P);
                kk[j][i] = R_PARAM * (1.0f - BETA_P) * v;
            }
    }

    const long long plane = (long long)(b * 8 + c) * NPLANE;
    const float* dpl = drive + plane;

    // this thread's single pair: rows r0 = 2ty, r1 = 2ty+1
    const int r0  = 2 * ty;
    const int r1  = r0 + 1;
    const int ir0 = rbase + r0;
    const int s0  = (ty == 0)         ? 16 : (r0 - 1);
    const int s3  = (ty == P_TYN - 1) ? 17 : (r1 + 1);

    // init: MB0 rows 0..15 <- mapped(drive)
    #pragma unroll
    for (int k = 0; k < 2; ++k) {
        int r = ty + P_TYN * k;
        const float* dr = dpl + (long long)(rbase + r) * W + x0;
        float4 dA = *reinterpret_cast<const float4*>(dr);
        float4 dB = *reinterpret_cast<const float4*>(dr + 4);
        float4 mA, mB;
        mA.x = fmaf(-dA.x, dA.x, dA.x);  mA.y = fmaf(-dA.y, dA.y, dA.y);
        mA.z = fmaf(-dA.z, dA.z, dA.z);  mA.w = fmaf(-dA.w, dA.w, dA.w);
        mB.x = fmaf(-dB.x, dB.x, dB.x);  mB.y = fmaf(-dB.y, dB.y, dB.y);
        mB.z = fmaf(-dB.z, dB.z, dB.z);  mB.w = fmaf(-dB.w, dB.w, dB.w);
        float* p0 = MB0 + r * W;
        *reinterpret_cast<float4*>(p0 + x4)       = mA;
        *reinterpret_cast<float4*>(p0 + 128 + x4) = mB;
    }
    CLUSTER_BAR();

    float sum[16], ssq[16];               // [rowInPair*8 + i]
    #pragma unroll
    for (int i = 0; i < 16; ++i) { sum[i] = 0.f; ssq[i] = 0.f; }

    #define ACCROW(acc, cc)                                                    \
        {                                                                      \
            float c0 = (cc)[0], c1 = (cc)[1], c2 = (cc)[2];                    \
            acc[0] = fmaf(c0, lm, fmaf(c1, m0, fmaf(c2, m1, acc[0])));         \
            acc[1] = fmaf(c0, m0, fmaf(c1, m1, fmaf(c2, m2, acc[1])));         \
            acc[2] = fmaf(c0, m1, fmaf(c1, m2, fmaf(c2, m3, acc[2])));         \
            acc[3] = fmaf(c0, m2, fmaf(c1, m3, fmaf(c2, m4, acc[3])));         \
            acc[4] = fmaf(c0, m3, fmaf(c1, m4, fmaf(c2, m5, acc[4])));         \
            acc[5] = fmaf(c0, m4, fmaf(c1, m5, fmaf(c2, m6, acc[5])));         \
            acc[6] = fmaf(c0, m5, fmaf(c1, m6, fmaf(c2, m7, acc[6])));         \
            acc[7] = fmaf(c0, m6, fmaf(c1, m7, fmaf(c2, rm, acc[7])));         \
        }

    #define LOAD_MROW(Min, slot)                                               \
        const float* rp = (Min) + (slot) * W;                                  \
        float4 qa = *reinterpret_cast<const float4*>(rp + x4);                 \
        float4 qb = *reinterpret_cast<const float4*>(rp + 128 + x4);           \
        float m0 = qa.x, m1 = qa.y, m2 = qa.z, m3 = qa.w;                      \
        float m4 = qb.x, m5 = qb.y, m6 = qb.z, m7 = qb.w;                      \
        float lm = __shfl_up_sync(0xffffffffu, m7, 1);                         \
        float rm = __shfl_down_sync(0xffffffffu, m0, 1);                       \
        if (tx == 0)  lm = 0.f;                                                \
        if (tx == 31) rm = 0.f;

    #define PAIR_CONV(Min, acc0, acc1)                                         \
        {                                                                      \
            { LOAD_MROW(Min, s0)  ACCROW(acc0, kk[0]) }                        \
            { LOAD_MROW(Min, r0)  ACCROW(acc0, kk[1]) ACCROW(acc1, kk[0]) }    \
            { LOAD_MROW(Min, r1)  ACCROW(acc0, kk[2]) ACCROW(acc1, kk[1]) }    \
            { LOAD_MROW(Min, s3)  ACCROW(acc1, kk[2]) }                        \
        }

    #define LOAD_DRIVE_BETA(ir, acc)                                           \
        {                                                                      \
            const float* dr = dpl + (long long)(ir) * W + x0;                  \
            float4 dA = *reinterpret_cast<const float4*>(dr);                  \
            float4 dB = *reinterpret_cast<const float4*>(dr + 4);              \
            acc[0] = BETA_P * dA.x;  acc[1] = BETA_P * dA.y;                   \
            acc[2] = BETA_P * dA.z;  acc[3] = BETA_P * dA.w;                   \
            acc[4] = BETA_P * dB.x;  acc[5] = BETA_P * dB.y;                   \
            acc[6] = BETA_P * dB.z;  acc[7] = BETA_P * dB.w;                   \
        }

    #define HALO_PROLOGUE(Min)                                                 \
        {                                                                      \
            if (ty == 0) {                                                     \
                float4 h0 = make_float4(0.f, 0.f, 0.f, 0.f), h1 = h0;          \
                if (strip > 0) {                                               \
                    uint32_t a = smem_u32((Min) + 15 * W + x4);                \
                    h0 = dsmem_ld4(a,       (uint32_t)(strip - 1));            \
                    h1 = dsmem_ld4(a + 512, (uint32_t)(strip - 1));            \
                }                                                              \
                *reinterpret_cast<float4*>((Min) + 16 * W + x4)       = h0;    \
                *reinterpret_cast<float4*>((Min) + 16 * W + 128 + x4) = h1;    \
            } else if (ty == P_TYN - 1) {                                      \
                float4 h0 = make_float4(0.f, 0.f, 0.f, 0.f), h1 = h0;          \
                if (strip < P_NSTRIP - 1) {                                    \
                    uint32_t a = smem_u32((Min) + x4);                         \
                    h0 = dsmem_ld4(a,       (uint32_t)(strip + 1));            \
                    h1 = dsmem_ld4(a + 512, (uint32_t)(strip + 1));            \
                }                                                              \
                *reinterpret_cast<float4*>((Min) + 17 * W + x4)       = h0;    \
                *reinterpret_cast<float4*>((Min) + 17 * W + 128 + x4) = h1;    \
            }                                                                  \
        }

    // steps 0..13
    #pragma unroll 1
    for (int t = 0; t < NSTEPS - 1; ++t) {
        float* Min  = (t & 1) ? MB1 : MB0;
        float* Mout = (t & 1) ? MB0 : MB1;

        HALO_PROLOGUE(Min)

        float acc0[8], acc1[8];
        LOAD_DRIVE_BETA(ir0, acc0)
        LOAD_DRIVE_BETA(ir0 + 1, acc1)

        PAIR_CONV(Min, acc0, acc1)

        // row-at-a-time epilogue: transient regs stay tiny (acc reused as mm)
        #pragma unroll
        for (int i = 0; i < 8; ++i) {
            float g = clampg(acc0[i]);
            sum[i] += g;  ssq[i] = fmaf(g, g, ssq[i]);
            acc0[i] = fmaf(-g, g, g);
        }
        float* op0 = Mout + r0 * W;
        *reinterpret_cast<float4*>(op0 + x4)       = make_float4(acc0[0], acc0[1], acc0[2], acc0[3]);
        *reinterpret_cast<float4*>(op0 + 128 + x4) = make_float4(acc0[4], acc0[5], acc0[6], acc0[7]);

        #pragma unroll
        for (int i = 0; i < 8; ++i) {
            float g = clampg(acc1[i]);
            sum[i + 8] += g;  ssq[i + 8] = fmaf(g, g, ssq[i + 8]);
            acc1[i] = fmaf(-g, g, g);
        }
        float* op1 = Mout + r1 * W;
        *reinterpret_cast<float4*>(op1 + x4)       = make_float4(acc1[0], acc1[1], acc1[2], acc1[3]);
        *reinterpret_cast<float4*>(op1 + 128 + x4) = make_float4(acc1[4], acc1[5], acc1[6], acc1[7]);

        CLUSTER_BAR();
    }

    // final step t=14 (reads MB0): write all 5 outputs
    {
        float* Min = MB0;
        const float inv = 1.0f / (float)NSTEPS;

        HALO_PROLOGUE(Min)

        float acc0[8] = {0.f,0.f,0.f,0.f,0.f,0.f,0.f,0.f};
        float acc1[8] = {0.f,0.f,0.f,0.f,0.f,0.f,0.f,0.f};
        PAIR_CONV(Min, acc0, acc1)

        #pragma unroll
        for (int half = 0; half < 2; ++half) {
            float* acc = half ? acc1 : acc0;
            const int off = half * 8;
            const int ir  = ir0 + half;
            long long idx = plane + (long long)ir * W + x0;

            const float* dr = dpl + (long long)ir * W + x0;
            float4 dA = *reinterpret_cast<const float4*>(dr);
            float4 dB = *reinterpret_cast<const float4*>(dr + 4);
            float dv[8] = { dA.x, dA.y, dA.z, dA.w, dB.x, dB.y, dB.z, dB.w };

            float g[8], mean[8], var[8], del[8];
            #pragma unroll
            for (int i = 0; i < 8; ++i) {
                g[i] = clampg(fmaf(BETA_P, dv[i], acc[i]));
                float s  = sum[off + i] + g[i];
                float sq = fmaf(g[i], g[i], ssq[off + i]);
                mean[i] = s * inv;
                var[i]  = fmaf(-mean[i], mean[i], sq * inv);
                del[i]  = g[i] - dv[i];
            }
            *reinterpret_cast<float4*>(out + idx)                = make_float4(g[0], g[1], g[2], g[3]);
            *reinterpret_cast<float4*>(out + idx + 4)            = make_float4(g[4], g[5], g[6], g[7]);
            *reinterpret_cast<float4*>(out + NTOT + idx)         = make_float4(mean[0], mean[1], mean[2], mean[3]);
            *reinterpret_cast<float4*>(out + NTOT + idx + 4)     = make_float4(mean[4], mean[5], mean[6], mean[7]);
            *reinterpret_cast<float4*>(out + 2 * NTOT + idx)     = make_float4(var[0], var[1], var[2], var[3]);
            *reinterpret_cast<float4*>(out + 2 * NTOT + idx + 4) = make_float4(var[4], var[5], var[6], var[7]);
            *reinterpret_cast<float4*>(out + 3 * NTOT + idx)     = make_float4(del[0], del[1], del[2], del[3]);
            *reinterpret_cast<float4*>(out + 3 * NTOT + idx + 4) = make_float4(del[4], del[5], del[6], del[7]);
            *reinterpret_cast<float4*>(out + 4 * NTOT + idx)     = make_float4(del[0], del[1], del[2], del[3]);
            *reinterpret_cast<float4*>(out + 4 * NTOT + idx + 4) = make_float4(del[4], del[5], del[6], del[7]);
        }
    }

    CLUSTER_BAR();

    #undef ACCROW
    #undef LOAD_MROW
    #undef PAIR_CONV
    #undef LOAD_DRIVE_BETA
    #undef HALO_PROLOGUE
}

// ===========================================================================
// FALLBACK: cml8 — round-10 kernel (cluster 8, 32-row strips, 2 pairs/thread)
// ===========================================================================

constexpr int F_RCTA   = 32;
constexpr int F_NSTRIP = 8;
constexpr int F_BROWS  = 34;
constexpr int F_TYN    = 8;
constexpr int F_NTHR   = 32 * F_TYN;           // 256
constexpr int F_BUF    = F_BROWS * W;          // 8704 floats
constexpr int F_SMEM   = 2 * F_BUF * 4;        // 69632 B

__global__ void __launch_bounds__(F_NTHR, 2) __cluster_dims__(F_NSTRIP, 1, 1)
cml8_kernel(const float* __restrict__ drive,
            const float* __restrict__ Klocal,
            float* __restrict__ out)
{
    extern __shared__ float sm[];
    float* MB0 = sm;
    float* MB1 = sm + F_BUF;

    const int tx = threadIdx.x;
    const int ty = threadIdx.y;
    const int strip = blockIdx.x;
    const int c     = blockIdx.y;
    const int b     = blockIdx.z;
    const int x4    = tx * 4;
    const int x0    = tx * 8;
    const int rbase = strip * F_RCTA;

    float kk[3][3];
    {
        const float* kc = Klocal + c * 9;
        #pragma unroll
        for (int j = 0; j < 3; ++j)
            #pragma unroll
            for (int i = 0; i < 3; ++i) {
                float v = EPS_P * kc[j * 3 + i];
                if (j == 1 && i == 1) v += (1.0f - EPS_P);
                kk[j][i] = R_PARAM * (1.0f - BETA_P) * v;
            }
    }

    const long long plane = (long long)(b * 8 + c) * NPLANE;
    const float* dpl = drive + plane;

    const int pA = (ty == 0) ? 8 : ty;
    const int pB = (ty == 0) ? 0 : ty + 8;
    const int A0 = 2 * pA - 1, A1 = 2 * pA, A2 = 2 * pA + 1, A3 = 2 * pA + 2;
    const int B0 = (pB == 0)  ? 32 : 2 * pB - 1;
    const int B1 = 2 * pB,     B2 = 2 * pB + 1;
    const int B3 = (pB == 15) ? 33 : 2 * pB + 2;
    const int irA = rbase + 2 * pA;
    const int irB = rbase + 2 * pB;

    #pragma unroll
    for (int k = 0; k < 4; ++k) {
        int r = ty + F_TYN * k;
        const float* dr = dpl + (long long)(rbase + r) * W + x0;
        float4 dA = *reinterpret_cast<const float4*>(dr);
        float4 dB = *reinterpret_cast<const float4*>(dr + 4);
        float4 mA, mB;
        mA.x = fmaf(-dA.x, dA.x, dA.x);  mA.y = fmaf(-dA.y, dA.y, dA.y);
        mA.z = fmaf(-dA.z, dA.z, dA.z);  mA.w = fmaf(-dA.w, dA.w, dA.w);
        mB.x = fmaf(-dB.x, dB.x, dB.x);  mB.y = fmaf(-dB.y, dB.y, dB.y);
        mB.z = fmaf(-dB.z, dB.z, dB.z);  mB.w = fmaf(-dB.w, dB.w, dB.w);
        float* p0 = MB0 + r * W;
        *reinterpret_cast<float4*>(p0 + x4)       = mA;
        *reinterpret_cast<float4*>(p0 + 128 + x4) = mB;
    }
    CLUSTER_BAR();

    float sumA[16], ssqA[16], sumB[16], ssqB[16];
    #pragma unroll
    for (int i = 0; i < 16; ++i) {
        sumA[i] = 0.f; ssqA[i] = 0.f; sumB[i] = 0.f; ssqB[i] = 0.f;
    }

    #define ACCROW_F(acc, cc)                                                  \
        {                                                                      \
            float c0 = (cc)[0], c1 = (cc)[1], c2 = (cc)[2];                    \
            acc[0] = fmaf(c0, lm, fmaf(c1, m0, fmaf(c2, m1, acc[0])));         \
            acc[1] = fmaf(c0, m0, fmaf(c1, m1, fmaf(c2, m2, acc[1])));         \
            acc[2] = fmaf(c0, m1, fmaf(c1, m2, fmaf(c2, m3, acc[2])));         \
            acc[3] = fmaf(c0, m2, fmaf(c1, m3, fmaf(c2, m4, acc[3])));         \
            acc[4] = fmaf(c0, m3, fmaf(c1, m4, fmaf(c2, m5, acc[4])));         \
            acc[5] = fmaf(c0, m4, fmaf(c1, m5, fmaf(c2, m6, acc[5])));         \
            acc[6] = fmaf(c0, m5, fmaf(c1, m6, fmaf(c2, m7, acc[6])));         \
            acc[7] = fmaf(c0, m6, fmaf(c1, m7, fmaf(c2, rm, acc[7])));         \
        }

    #define PAIR_CONV_F(Min, R0, R1, R2, R3, acc0, acc1)                       \
        {                                                                      \
            const int rows_[4] = { (R0), (R1), (R2), (R3) };                   \
            _Pragma("unroll")                                                  \
            for (int jr = 0; jr < 4; ++jr) {                                   \
                const float* rp = (Min) + rows_[jr] * W;                       \
                float4 qa = *reinterpret_cast<const float4*>(rp + x4);         \
                float4 qb = *reinterpret_cast<const float4*>(rp + 128 + x4);   \
                float m0 = qa.x, m1 = qa.y, m2 = qa.z, m3 = qa.w;              \
                float m4 = qb.x, m5 = qb.y, m6 = qb.z, m7 = qb.w;              \
                float lm = __shfl_up_sync(0xffffffffu, m7, 1);                 \
                float rm = __shfl_down_sync(0xffffffffu, m0, 1);               \
                if (tx == 0)  lm = 0.f;                                        \
                if (tx == 31) rm = 0.f;                                        \
                if (jr < 3) ACCROW_F(acc0, kk[jr])                             \
                if (jr > 0) ACCROW_F(acc1, kk[jr - 1])                         \
            }                                                                  \
        }

    #define LOAD_DRIVE_RAW_F(ir, dv)                                           \
        {                                                                      \
            const float* dr = dpl + (long long)(ir) * W + x0;                  \
            float4 dA = *reinterpret_cast<const float4*>(dr);                  \
            float4 dB = *reinterpret_cast<const float4*>(dr + 4);              \
            dv[0] = dA.x;  dv[1] = dA.y;  dv[2] = dA.z;  dv[3] = dA.w;         \
            dv[4] = dB.x;  dv[5] = dB.y;  dv[6] = dB.z;  dv[7] = dB.w;         \
        }

    #define HALO_PROLOGUE_F(Min)                                               \
        {                                                                      \
            if (ty == 0) {                                                     \
                float4 h0 = make_float4(0.f, 0.f, 0.f, 0.f), h1 = h0;          \
                if (strip > 0) {                                               \
                    uint32_t a = smem_u32((Min) + 31 * W + x4);                \
                    h0 = dsmem_ld4(a,       (uint32_t)(strip - 1));            \
                    h1 = dsmem_ld4(a + 512, (uint32_t)(strip - 1));            \
                }                                                              \
                *reinterpret_cast<float4*>((Min) + 32 * W + x4)       = h0;    \
                *reinterpret_cast<float4*>((Min) + 32 * W + 128 + x4) = h1;    \
            } else if (ty == F_TYN - 1) {                                      \
                float4 h0 = make_float4(0.f, 0.f, 0.f, 0.f), h1 = h0;          \
                if (strip < F_NSTRIP - 1) {                                    \
                    uint32_t a = smem_u32((Min) + x4);                         \
                    h0 = dsmem_ld4(a,       (uint32_t)(strip + 1));            \
                    h1 = dsmem_ld4(a + 512, (uint32_t)(strip + 1));            \
                }                                                              \
                *reinterpret_cast<float4*>((Min) + 33 * W + x4)       = h0;    \
                *reinterpret_cast<float4*>((Min) + 33 * W + 128 + x4) = h1;    \
            }                                                                  \
        }

    #define PAIR_STEP_F(Min, Mout, R0, R1, R2, R3, irr, orow, sumP, ssqP)      \
        {                                                                      \
            float dv0[8], dv1[8];                                              \
            LOAD_DRIVE_RAW_F((irr), dv0)                                       \
            LOAD_DRIVE_RAW_F((irr) + 1, dv1)                                   \
            float acc0[8] = {0.f,0.f,0.f,0.f,0.f,0.f,0.f,0.f};                 \
            float acc1[8] = {0.f,0.f,0.f,0.f,0.f,0.f,0.f,0.f};                 \
            PAIR_CONV_F(Min, R0, R1, R2, R3, acc0, acc1)                       \
            float g0[8], g1[8], mm0[8], mm1[8];                                \
            _Pragma("unroll")                                                  \
            for (int i = 0; i < 8; ++i) {                                      \
                g0[i]  = clampg(fmaf(BETA_P, dv0[i], acc0[i]));                \
                g1[i]  = clampg(fmaf(BETA_P, dv1[i], acc1[i]));                \
                mm0[i] = fmaf(-g0[i], g0[i], g0[i]);                           \
                mm1[i] = fmaf(-g1[i], g1[i], g1[i]);                           \
                sumP[i]     += g0[i];  ssqP[i]     = fmaf(g0[i], g0[i], ssqP[i]);      \
                sumP[i + 8] += g1[i];  ssqP[i + 8] = fmaf(g1[i], g1[i], ssqP[i + 8]);  \
            }                                                                  \
            float* op0 = (Mout) + (orow) * W;                                  \
            float* op1 = (Mout) + ((orow) + 1) * W;                            \
            *reinterpret_cast<float4*>(op0 + x4)       = make_float4(mm0[0], mm0[1], mm0[2], mm0[3]); \
            *reinterpret_cast<float4*>(op0 + 128 + x4) = make_float4(mm0[4], mm0[5], mm0[6], mm0[7]); \
            *reinterpret_cast<float4*>(op1 + x4)       = make_float4(mm1[0], mm1[1], mm1[2], mm1[3]); \
            *reinterpret_cast<float4*>(op1 + 128 + x4) = make_float4(mm1[4], mm1[5], mm1[6], mm1[7]); \
        }

    #pragma unroll 1
    for (int t = 0; t < NSTEPS - 1; ++t) {
        float* Min  = (t & 1) ? MB1 : MB0;
        float* Mout = (t & 1) ? MB0 : MB1;

        HALO_PROLOGUE_F(Min)
        PAIR_STEP_F(Min, Mout, A0, A1, A2, A3, irA, 2 * pA, sumA, ssqA)
        PAIR_STEP_F(Min, Mout, B0, B1, B2, B3, irB, 2 * pB, sumB, ssqB)
        CLUSTER_BAR();
    }

    {
        float* Min = MB0;
        const float inv = 1.0f / (float)NSTEPS;

        HALO_PROLOGUE_F(Min)

        #pragma unroll
        for (int pp = 0; pp < 2; ++pp) {
            const int irr  = pp ? irB : irA;
            float* sumP = pp ? sumB : sumA;
            float* ssqP = pp ? ssqB : ssqA;

            float dv0[8], dv1[8];
            LOAD_DRIVE_RAW_F(irr, dv0)
            LOAD_DRIVE_RAW_F(irr + 1, dv1)

            float acc0[8] = {0.f,0.f,0.f,0.f,0.f,0.f,0.f,0.f};
            float acc1[8] = {0.f,0.f,0.f,0.f,0.f,0.f,0.f,0.f};
            if (pp == 0) { PAIR_CONV_F(Min, A0, A1, A2, A3, acc0, acc1) }
            else         { PAIR_CONV_F(Min, B0, B1, B2, B3, acc0, acc1) }

            #pragma unroll
            for (int half = 0; half < 2; ++half) {
                const float* acc = half ? acc1 : acc0;
                const float* dv  = half ? dv1  : dv0;
                const int off    = half * 8;
                long long idx = plane + (long long)(irr + half) * W + x0;

                float g[8], mean[8], var[8], del[8];
                #pragma unroll
                for (int i = 0; i < 8; ++i) {
                    g[i] = clampg(fmaf(BETA_P, dv[i], acc[i]));
                    float s  = sumP[off + i] + g[i];
                    float sq = fmaf(g[i], g[i], ssqP[off + i]);
                    mean[i] = s * inv;
                    var[i]  = fmaf(-mean[i], mean[i], sq * inv);
                    del[i]  = g[i] - dv[i];
                }
                *reinterpret_cast<float4*>(out + idx)                = make_float4(g[0], g[1], g[2], g[3]);
                *reinterpret_cast<float4*>(out + idx + 4)            = make_float4(g[4], g[5], g[6], g[7]);
                *reinterpret_cast<float4*>(out + NTOT + idx)         = make_float4(mean[0], mean[1], mean[2], mean[3]);
                *reinterpret_cast<float4*>(out + NTOT + idx + 4)     = make_float4(mean[4], mean[5], mean[6], mean[7]);
                *reinterpret_cast<float4*>(out + 2 * NTOT + idx)     = make_float4(var[0], var[1], var[2], var[3]);
                *reinterpret_cast<float4*>(out + 2 * NTOT + idx + 4) = make_float4(var[4], var[5], var[6], var[7]);
                *reinterpret_cast<float4*>(out + 3 * NTOT + idx)     = make_float4(del[0], del[1], del[2], del[3]);
                *reinterpret_cast<float4*>(out + 3 * NTOT + idx + 4) = make_float4(del[4], del[5], del[6], del[7]);
                *reinterpret_cast<float4*>(out + 4 * NTOT + idx)     = make_float4(del[0], del[1], del[2], del[3]);
                *reinterpret_cast<float4*>(out + 4 * NTOT + idx + 4) = make_float4(del[4], del[5], del[6], del[7]);
            }
        }
    }

    CLUSTER_BAR();
}

// ===========================================================================
// Host: validate cluster-16 support, else fall back to cluster-8.
// Stateless + deterministic: the same checks run on every call.
// ===========================================================================

extern "C" void kernel_launch(void* const* d_in, const int* in_sizes, int n_in,
                              void* d_out, int out_size)
{
    const float* drive  = (const float*)d_in[0];   // [16,8,256,256] f32
    const float* Klocal = (const float*)d_in[1];   // [8,1,3,3] f32
    float* out = (float*)d_out;                    // 5 x [16,8,256,256] f32

    bool use16 = true;
    if (cudaFuncSetAttribute(cml16_kernel,
            cudaFuncAttributeMaxDynamicSharedMemorySize, P_SMEM) != cudaSuccess)
        use16 = false;
    if (use16 && cudaFuncSetAttribute(cml16_kernel,
            cudaFuncAttributeNonPortableClusterSizeAllowed, 1) != cudaSuccess)
        use16 = false;

    if (use16) {
        cudaLaunchConfig_t cfg = {};
        cfg.gridDim  = dim3(P_NSTRIP, 8, 16);
        cfg.blockDim = dim3(32, P_TYN, 1);
        cfg.dynamicSmemBytes = P_SMEM;
        cudaLaunchAttribute at[1];
        at[0].id = cudaLaunchAttributeClusterDimension;
        at[0].val.clusterDim.x = P_NSTRIP;
        at[0].val.clusterDim.y = 1;
        at[0].val.clusterDim.z = 1;
        cfg.attrs = at;
        cfg.numAttrs = 1;
        int nclust = 0;
        if (cudaOccupancyMaxActiveClusters(&nclust, cml16_kernel, &cfg) != cudaSuccess
            || nclust < 1)
            use16 = false;
    }
    (void)cudaGetLastError();   // clear any sticky error from failed probes

    if (use16) {
        dim3 grid(P_NSTRIP, 8, 16);    // 16 strips x 8 ch x 16 b = 2048 CTAs
        dim3 block(32, P_TYN);         // 256 threads
        cml16_kernel<<<grid, block, P_SMEM>>>(drive, Klocal, out);
    } else {
        cudaFuncSetAttribute(cml8_kernel,
            cudaFuncAttributeMaxDynamicSharedMemorySize, F_SMEM);
        dim3 grid(F_NSTRIP, 8, 16);    // 8 strips x 8 ch x 16 b = 1024 CTAs
        dim3 block(32, F_TYN);         // 256 threads
        cml8_kernel<<<grid, block, F_SMEM>>>(drive, Klocal, out);
    }
}

// round 13
// speedup vs baseline: 1.0075x; 1.0075x over previous
#include <cuda_runtime.h>
#include <cstdint>

// ---------------------------------------------------------------------------
// CML2DWithStats, round 13: cluster-4 (r7 geometry) with TWO steps fused per
// cluster barrier via 3-row halo + one-step halo recompute.
//
//   g_{t+1} = clamp( conv3x3( m_t, K' ) + BETA*drive ),  m = g*(1-g)
//   K' = R*(1-BETA)*(EPS*K + (1-EPS)*delta_center)
//
// Cluster (4,1,1) per plane; rank = 64-row strip. Buffers MB0/MB1 hold 70
// rows: buffer row r <-> image row rbase + r - 3 (own rows = buffer 3..66).
// Super-step s (steps 2s, 2s+1):
//   1. pull 3 halo rows/side of MB0 from neighbors (DSMEM), __syncthreads
//   2. step A: MB0 -> MB1 over buffer rows 1..68 (own 34 pairs incl. 2 extra
//      halo pairs by ty 7/8; extras are bit-identical recomputes of neighbor
//      rows, no stats), __syncthreads
//   3. step B: MB1 -> MB0 over own rows 3..66 (32 pairs), cluster barrier.
// MB0 is ALWAYS the step input. 7 super-steps cover steps 0..13; final step
// 14 pulls a 1-row halo and writes the 5 outputs.
// Barrier count: 15 cluster bars -> 8 (+14 cheap __syncthreads).
// ---------------------------------------------------------------------------

#define R_PARAM  3.9f
#define EPS_P    0.3f
#define BETA_P   0.15f
#define NSTEPS   15
#define CLAMP_LO 1e-4f
#define CLAMP_HI (1.0f - 1e-4f)

constexpr int W      = 256;
constexpr int RCTA   = 64;
constexpr int NSTRIP = 4;
constexpr int BROWS  = 70;                 // 3 halo + 64 own + 3 halo
constexpr int TXN    = 32;
constexpr int TYN    = 16;
constexpr int NTHR   = TXN * TYN;          // 512
constexpr int NPLANE = W * 256;
constexpr long long NTOT = 16LL * 8 * NPLANE;
constexpr int BUF        = BROWS * W;          // 17920 floats
constexpr int SMEM_BYTES = 2 * BUF * 4;        // 143360 B

__device__ __forceinline__ float clampg(float v) {
    return fminf(fmaxf(v, CLAMP_LO), CLAMP_HI);
}

__device__ __forceinline__ uint32_t smem_u32(const void* p) {
    uint32_t a;
    asm("{ .reg .u64 t; cvta.to.shared.u64 t, %1; cvt.u32.u64 %0, t; }"
        : "=r"(a) : "l"(p));
    return a;
}

__device__ __forceinline__ float4 dsmem_ld4(uint32_t my_addr, uint32_t rank) {
    uint32_t ra; float4 v;
    asm volatile("mapa.shared::cluster.u32 %0, %1, %2;"
                 : "=r"(ra) : "r"(my_addr), "r"(rank));
    asm volatile("ld.shared::cluster.v4.f32 {%0, %1, %2, %3}, [%4];"
                 : "=f"(v.x), "=f"(v.y), "=f"(v.z), "=f"(v.w) : "r"(ra));
    return v;
}

#define CLUSTER_BAR()                                                       \
    do {                                                                    \
        asm volatile("barrier.cluster.arrive.aligned;" ::: "memory");       \
        asm volatile("barrier.cluster.wait.aligned;"   ::: "memory");       \
    } while (0)

__global__ void __launch_bounds__(NTHR, 1) __cluster_dims__(NSTRIP, 1, 1)
cml_fused2_kernel(const float* __restrict__ drive,
                  const float* __restrict__ Klocal,
                  float* __restrict__ out)
{
    extern __shared__ float sm[];
    float* MB0 = sm;
    float* MB1 = sm + BUF;

    const int tx = threadIdx.x;
    const int ty = threadIdx.y;
    const int strip = blockIdx.x;          // cluster rank 0..3
    const int c     = blockIdx.y;
    const int b     = blockIdx.z;
    const int x4    = tx * 4;
    const int x0    = tx * 8;
    const int rbase = strip * RCTA;

    // Folded kernel K' = R*(1-BETA)*(EPS*K + (1-EPS)*delta)
    float kk[3][3];
    {
        const float* kc = Klocal + c * 9;
        #pragma unroll
        for (int j = 0; j < 3; ++j)
            #pragma unroll
            for (int i = 0; i < 3; ++i) {
                float v = EPS_P * kc[j * 3 + i];
                if (j == 1 && i == 1) v += (1.0f - EPS_P);
                kk[j][i] = R_PARAM * (1.0f - BETA_P) * v;
            }
    }

    const long long plane = (long long)(b * 8 + c) * NPLANE;
    const float* dpl = drive + plane;

    // own pairs (same buffer rows in step A and step B -> stats stay in-thread)
    const int rP0  = 3 + 2 * ty;               // pair rows rP0, rP0+1
    const int rP1  = 35 + 2 * ty;
    const int irP0 = rbase + 2 * ty;           // image rows
    const int irP1 = rbase + 32 + 2 * ty;

    // ---- init: MB0 own rows (buffer 3..66) <- mapped(drive) ----
    #pragma unroll
    for (int k = 0; k < 4; ++k) {
        int r = ty + TYN * k;                  // 0..63
        const float* dr = dpl + (long long)(rbase + r) * W + x0;
        float4 dA = *reinterpret_cast<const float4*>(dr);
        float4 dB = *reinterpret_cast<const float4*>(dr + 4);
        float4 mA, mB;
        mA.x = fmaf(-dA.x, dA.x, dA.x);  mA.y = fmaf(-dA.y, dA.y, dA.y);
        mA.z = fmaf(-dA.z, dA.z, dA.z);  mA.w = fmaf(-dA.w, dA.w, dA.w);
        mB.x = fmaf(-dB.x, dB.x, dB.x);  mB.y = fmaf(-dB.y, dB.y, dB.y);
        mB.z = fmaf(-dB.z, dB.z, dB.z);  mB.w = fmaf(-dB.w, dB.w, dB.w);
        float* p0 = MB0 + (r + 3) * W;
        *reinterpret_cast<float4*>(p0 + x4)       = mA;
        *reinterpret_cast<float4*>(p0 + 128 + x4) = mB;
    }
    CLUSTER_BAR();

    // stats: [rowInPair*8 + i] per own pair
    float sum0[16], ssq0[16], sum1[16], ssq1[16];
    #pragma unroll
    for (int i = 0; i < 16; ++i) {
        sum0[i] = 0.f; ssq0[i] = 0.f; sum1[i] = 0.f; ssq1[i] = 0.f;
    }

    #define ACCROW(acc, cc)                                                    \
        {                                                                      \
            float c0 = (cc)[0], c1 = (cc)[1], c2 = (cc)[2];                    \
            acc[0] = fmaf(c0, lm, fmaf(c1, m0, fmaf(c2, m1, acc[0])));         \
            acc[1] = fmaf(c0, m0, fmaf(c1, m1, fmaf(c2, m2, acc[1])));         \
            acc[2] = fmaf(c0, m1, fmaf(c1, m2, fmaf(c2, m3, acc[2])));         \
            acc[3] = fmaf(c0, m2, fmaf(c1, m3, fmaf(c2, m4, acc[3])));         \
            acc[4] = fmaf(c0, m3, fmaf(c1, m4, fmaf(c2, m5, acc[4])));         \
            acc[5] = fmaf(c0, m4, fmaf(c1, m5, fmaf(c2, m6, acc[5])));         \
            acc[6] = fmaf(c0, m5, fmaf(c1, m6, fmaf(c2, m7, acc[6])));         \
            acc[7] = fmaf(c0, m6, fmaf(c1, m7, fmaf(c2, rm, acc[7])));         \
        }

    // conv of pair (rr, rr+1): reads Src rows rr-1..rr+2
    #define PAIR_CONV(Src, rr, acc0, acc1)                                     \
        {                                                                      \
            _Pragma("unroll")                                                  \
            for (int jr = 0; jr < 4; ++jr) {                                   \
                const float* rp = (Src) + ((rr) - 1 + jr) * W;                 \
                float4 qa = *reinterpret_cast<const float4*>(rp + x4);         \
                float4 qb = *reinterpret_cast<const float4*>(rp + 128 + x4);   \
                float m0 = qa.x, m1 = qa.y, m2 = qa.z, m3 = qa.w;              \
                float m4 = qb.x, m5 = qb.y, m6 = qb.z, m7 = qb.w;              \
                float lm = __shfl_up_sync(0xffffffffu, m7, 1);                 \
                float rm = __shfl_down_sync(0xffffffffu, m0, 1);               \
                if (tx == 0)  lm = 0.f;                                        \
                if (tx == 31) rm = 0.f;                                        \
                if (jr < 3) ACCROW(acc0, kk[jr])                               \
                if (jr > 0) ACCROW(acc1, kk[jr - 1])                           \
            }                                                                  \
        }

    #define LOAD_DRIVE_BETA(ir, acc)                                           \
        {                                                                      \
            const float* dr = dpl + (long long)(ir) * W + x0;                  \
            float4 dA = *reinterpret_cast<const float4*>(dr);                  \
            float4 dB = *reinterpret_cast<const float4*>(dr + 4);              \
            acc[0] = BETA_P * dA.x;  acc[1] = BETA_P * dA.y;                   \
            acc[2] = BETA_P * dA.z;  acc[3] = BETA_P * dA.w;                   \
            acc[4] = BETA_P * dB.x;  acc[5] = BETA_P * dB.y;                   \
            acc[6] = BETA_P * dB.z;  acc[7] = BETA_P * dB.w;                   \
        }

    // full pair with stats: Src -> Dst, rows (rr, rr+1), image rows (ir, ir+1)
    #define PAIR_STEP(Src, Dst, rr, ir, sumP, ssqP)                            \
        {                                                                      \
            float acc0[8], acc1[8];                                            \
            LOAD_DRIVE_BETA((ir), acc0)                                        \
            LOAD_DRIVE_BETA((ir) + 1, acc1)                                    \
            PAIR_CONV(Src, rr, acc0, acc1)                                     \
            _Pragma("unroll")                                                  \
            for (int i = 0; i < 8; ++i) {                                      \
                float g = clampg(acc0[i]);                                     \
                sumP[i] += g;  ssqP[i] = fmaf(g, g, ssqP[i]);                  \
                acc0[i] = fmaf(-g, g, g);                                      \
            }                                                                  \
            _Pragma("unroll")                                                  \
            for (int i = 0; i < 8; ++i) {                                      \
                float g = clampg(acc1[i]);                                     \
                sumP[i + 8] += g;  ssqP[i + 8] = fmaf(g, g, ssqP[i + 8]);      \
                acc1[i] = fmaf(-g, g, g);                                      \
            }                                                                  \
            float* op0 = (Dst) + (rr) * W;                                     \
            float* op1 = (Dst) + ((rr) + 1) * W;                               \
            *reinterpret_cast<float4*>(op0 + x4)       = make_float4(acc0[0], acc0[1], acc0[2], acc0[3]); \
            *reinterpret_cast<float4*>(op0 + 128 + x4) = make_float4(acc0[4], acc0[5], acc0[6], acc0[7]); \
            *reinterpret_cast<float4*>(op1 + x4)       = make_float4(acc1[0], acc1[1], acc1[2], acc1[3]); \
            *reinterpret_cast<float4*>(op1 + 128 + x4) = make_float4(acc1[4], acc1[5], acc1[6], acc1[7]); \
        }

    // halo-recompute pair (no stats)
    #define PAIR_EXTRA(Src, Dst, rr, ir)                                       \
        {                                                                      \
            float acc0[8], acc1[8];                                            \
            LOAD_DRIVE_BETA((ir), acc0)                                        \
            LOAD_DRIVE_BETA((ir) + 1, acc1)                                    \
            PAIR_CONV(Src, rr, acc0, acc1)                                     \
            _Pragma("unroll")                                                  \
            for (int i = 0; i < 8; ++i) {                                      \
                float g = clampg(acc0[i]);  acc0[i] = fmaf(-g, g, g);          \
                g = clampg(acc1[i]);        acc1[i] = fmaf(-g, g, g);          \
            }                                                                  \
            float* op0 = (Dst) + (rr) * W;                                     \
            float* op1 = (Dst) + ((rr) + 1) * W;                               \
            *reinterpret_cast<float4*>(op0 + x4)       = make_float4(acc0[0], acc0[1], acc0[2], acc0[3]); \
            *reinterpret_cast<float4*>(op0 + 128 + x4) = make_float4(acc0[4], acc0[5], acc0[6], acc0[7]); \
            *reinterpret_cast<float4*>(op1 + x4)       = make_float4(acc1[0], acc1[1], acc1[2], acc1[3]); \
            *reinterpret_cast<float4*>(op1 + 128 + x4) = make_float4(acc1[4], acc1[5], acc1[6], acc1[7]); \
        }

    #define ZPAIR(Dst, rr)                                                     \
        {                                                                      \
            float4 z = make_float4(0.f, 0.f, 0.f, 0.f);                        \
            float* op0 = (Dst) + (rr) * W;                                     \
            float* op1 = (Dst) + ((rr) + 1) * W;                               \
            *reinterpret_cast<float4*>(op0 + x4)       = z;                    \
            *reinterpret_cast<float4*>(op0 + 128 + x4) = z;                    \
            *reinterpret_cast<float4*>(op1 + x4)       = z;                    \
            *reinterpret_cast<float4*>(op1 + 128 + x4) = z;                    \
        }

    // ---- 7 super-steps = steps 0..13 ----
    #pragma unroll 1
    for (int s = 0; s < 7; ++s) {
        // 1. pull 3 halo rows/side of MB0 (neighbors' B-output, ordered by
        //    the cluster barrier that ended the previous super-step)
        if (ty == 0) {
            #pragma unroll
            for (int j = 0; j < 3; ++j) {
                float4 h0 = make_float4(0.f, 0.f, 0.f, 0.f), h1 = h0;
                if (strip > 0) {
                    uint32_t a = smem_u32(MB0 + (64 + j) * W + x4);
                    h0 = dsmem_ld4(a,       (uint32_t)(strip - 1));
                    h1 = dsmem_ld4(a + 512, (uint32_t)(strip - 1));
                }
                *reinterpret_cast<float4*>(MB0 + j * W + x4)       = h0;
                *reinterpret_cast<float4*>(MB0 + j * W + 128 + x4) = h1;
            }
        } else if (ty == TYN - 1) {
            #pragma unroll
            for (int j = 0; j < 3; ++j) {
                float4 h0 = make_float4(0.f, 0.f, 0.f, 0.f), h1 = h0;
                if (strip < NSTRIP - 1) {
                    uint32_t a = smem_u32(MB0 + (3 + j) * W + x4);
                    h0 = dsmem_ld4(a,       (uint32_t)(strip + 1));
                    h1 = dsmem_ld4(a + 512, (uint32_t)(strip + 1));
                }
                *reinterpret_cast<float4*>(MB0 + (67 + j) * W + x4)       = h0;
                *reinterpret_cast<float4*>(MB0 + (67 + j) * W + 128 + x4) = h1;
            }
        }
        __syncthreads();

        // 2. step A (t = 2s): MB0 -> MB1 over rows 1..68
        PAIR_STEP(MB0, MB1, rP0, irP0, sum0, ssq0)
        PAIR_STEP(MB0, MB1, rP1, irP1, sum1, ssq1)
        if (ty == 7) {
            if (strip > 0) { PAIR_EXTRA(MB0, MB1, 1, rbase - 2) }
            else           { ZPAIR(MB1, 1) }
        } else if (ty == 8) {
            if (strip < NSTRIP - 1) { PAIR_EXTRA(MB0, MB1, 67, rbase + 64) }
            else                    { ZPAIR(MB1, 67) }
        }
        __syncthreads();

        // 3. step B (t = 2s+1): MB1 -> MB0 over own rows 3..66
        PAIR_STEP(MB1, MB0, rP0, irP0, sum0, ssq0)
        PAIR_STEP(MB1, MB0, rP1, irP1, sum1, ssq1)
        CLUSTER_BAR();
    }

    // ---- final step t=14: 1-row halo, compute own pairs, write 5 outputs ----
    {
        if (ty == 0) {
            float4 h0 = make_float4(0.f, 0.f, 0.f, 0.f), h1 = h0;
            if (strip > 0) {
                uint32_t a = smem_u32(MB0 + 66 * W + x4);
                h0 = dsmem_ld4(a,       (uint32_t)(strip - 1));
                h1 = dsmem_ld4(a + 512, (uint32_t)(strip - 1));
            }
            *reinterpret_cast<float4*>(MB0 + 2 * W + x4)       = h0;
            *reinterpret_cast<float4*>(MB0 + 2 * W + 128 + x4) = h1;
        } else if (ty == TYN - 1) {
            float4 h0 = make_float4(0.f, 0.f, 0.f, 0.f), h1 = h0;
            if (strip < NSTRIP - 1) {
                uint32_t a = smem_u32(MB0 + 3 * W + x4);
                h0 = dsmem_ld4(a,       (uint32_t)(strip + 1));
                h1 = dsmem_ld4(a + 512, (uint32_t)(strip + 1));
            }
            *reinterpret_cast<float4*>(MB0 + 67 * W + x4)       = h0;
            *reinterpret_cast<float4*>(MB0 + 67 * W + 128 + x4) = h1;
        }
        __syncthreads();

        const float inv = 1.0f / (float)NSTEPS;

        #pragma unroll
        for (int pp = 0; pp < 2; ++pp) {
            const int rr  = pp ? rP1 : rP0;
            const int irr = pp ? irP1 : irP0;
            float* sumP = pp ? sum1 : sum0;
            float* ssqP = pp ? ssq1 : ssq0;

            float acc0[8] = {0.f,0.f,0.f,0.f,0.f,0.f,0.f,0.f};
            float acc1[8] = {0.f,0.f,0.f,0.f,0.f,0.f,0.f,0.f};
            PAIR_CONV(MB0, rr, acc0, acc1)

            #pragma unroll
            for (int half = 0; half < 2; ++half) {
                float* acc = half ? acc1 : acc0;
                const int off = half * 8;
                const int ir  = irr + half;
                long long idx = plane + (long long)ir * W + x0;

                const float* dr = dpl + (long long)ir * W + x0;
                float4 dA = *reinterpret_cast<const float4*>(dr);
                float4 dB = *reinterpret_cast<const float4*>(dr + 4);
                float dv[8] = { dA.x, dA.y, dA.z, dA.w, dB.x, dB.y, dB.z, dB.w };

                float g[8], mean[8], var[8], del[8];
                #pragma unroll
                for (int i = 0; i < 8; ++i) {
                    g[i] = clampg(fmaf(BETA_P, dv[i], acc[i]));
                    float sv = sumP[off + i] + g[i];
                    float sq = fmaf(g[i], g[i], ssqP[off + i]);
                    mean[i] = sv * inv;
                    var[i]  = fmaf(-mean[i], mean[i], sq * inv);
                    del[i]  = g[i] - dv[i];
                }
                *reinterpret_cast<float4*>(out + idx)                = make_float4(g[0], g[1], g[2], g[3]);
                *reinterpret_cast<float4*>(out + idx + 4)            = make_float4(g[4], g[5], g[6], g[7]);
                *reinterpret_cast<float4*>(out + NTOT + idx)         = make_float4(mean[0], mean[1], mean[2], mean[3]);
                *reinterpret_cast<float4*>(out + NTOT + idx + 4)     = make_float4(mean[4], mean[5], mean[6], mean[7]);
                *reinterpret_cast<float4*>(out + 2 * NTOT + idx)     = make_float4(var[0], var[1], var[2], var[3]);
                *reinterpret_cast<float4*>(out + 2 * NTOT + idx + 4) = make_float4(var[4], var[5], var[6], var[7]);
                *reinterpret_cast<float4*>(out + 3 * NTOT + idx)     = make_float4(del[0], del[1], del[2], del[3]);
                *reinterpret_cast<float4*>(out + 3 * NTOT + idx + 4) = make_float4(del[4], del[5], del[6], del[7]);
                *reinterpret_cast<float4*>(out + 4 * NTOT + idx)     = make_float4(del[0], del[1], del[2], del[3]);
                *reinterpret_cast<float4*>(out + 4 * NTOT + idx + 4) = make_float4(del[4], del[5], del[6], del[7]);
            }
        }
    }

    // no CTA may exit while a neighbor might still read its smem
    CLUSTER_BAR();
}

extern "C" void kernel_launch(void* const* d_in, const int* in_sizes, int n_in,
                              void* d_out, int out_size)
{
    const float* drive  = (const float*)d_in[0];   // [16,8,256,256] f32
    const float* Klocal = (const float*)d_in[1];   // [8,1,3,3] f32
    float* out = (float*)d_out;                    // 5 x [16,8,256,256] f32

    cudaFuncSetAttribute(cml_fused2_kernel,
                         cudaFuncAttributeMaxDynamicSharedMemorySize, SMEM_BYTES);

    dim3 grid(NSTRIP, 8, 16);          // 4 strips (1 cluster/plane) x 8 ch x 16 b
    dim3 block(TXN, TYN);              // 512 threads
    cml_fused2_kernel<<<grid, block, SMEM_BYTES>>>(drive, Klocal, out);
}

// round 14
// speedup vs baseline: 1.4383x; 1.4276x over previous
#include <cuda_runtime.h>
#include <cstdint>

// ---------------------------------------------------------------------------
// CML2DWithStats, round 14: r7 base (cluster-4, DSMEM halo, 2 pairs/thread)
// + beta*drive precomputed into smem (DS tile) -> zero per-step global loads.
//
//   g_{t+1} = clamp( conv3x3( m_t, K' ) + BETA*drive ),  m = g*(1-g)
//   K' = R*(1-BETA)*(EPS*K + (1-EPS)*delta_center)
//
// Cluster (4,1,1) per plane; rank = 64-row strip. Per-CTA smem:
//   MB0/MB1: two 66-row mapped buffers (rows 0..63 own, 64/65 halo slots)
//   DS:      64-row beta*drive tile (filled once at init)
// Per step: halo pull (warps ty 0/15, sole readers of their slots) ->
// pair A (interior) -> pair B (boundary) -> cluster barrier.
// acc is initialized from DS via LDS (29 cyc) instead of LDG (~240 cyc after
// the per-step cluster-release L1 flush) -- removes 8 LDG.128 + 32 FMUL +
// global addressing per thread-step.
// ---------------------------------------------------------------------------

#define R_PARAM  3.9f
#define EPS_P    0.3f
#define BETA_P   0.15f
#define NSTEPS   15
#define CLAMP_LO 1e-4f
#define CLAMP_HI (1.0f - 1e-4f)

constexpr int W      = 256;
constexpr int RCTA   = 64;
constexpr int NSTRIP = 4;
constexpr int BROWS  = 66;                 // 64 own + 2 halo slots
constexpr int TXN    = 32;
constexpr int TYN    = 16;
constexpr int NTHR   = TXN * TYN;          // 512
constexpr int NPLANE = W * 256;
constexpr long long NTOT = 16LL * 8 * NPLANE;
constexpr int BUF        = BROWS * W;                  // 16896 floats
constexpr int DS_OFF     = 2 * BUF;                    // DS tile offset (floats)
constexpr int SMEM_BYTES = (2 * BUF + RCTA * W) * 4;   // 200704 B

__device__ __forceinline__ float clampg(float v) {
    return fminf(fmaxf(v, CLAMP_LO), CLAMP_HI);
}

__device__ __forceinline__ uint32_t smem_u32(const void* p) {
    uint32_t a;
    asm("{ .reg .u64 t; cvta.to.shared.u64 t, %1; cvt.u32.u64 %0, t; }"
        : "=r"(a) : "l"(p));
    return a;
}

__device__ __forceinline__ float4 dsmem_ld4(uint32_t my_addr, uint32_t rank) {
    uint32_t ra; float4 v;
    asm volatile("mapa.shared::cluster.u32 %0, %1, %2;"
                 : "=r"(ra) : "r"(my_addr), "r"(rank));
    asm volatile("ld.shared::cluster.v4.f32 {%0, %1, %2, %3}, [%4];"
                 : "=f"(v.x), "=f"(v.y), "=f"(v.z), "=f"(v.w) : "r"(ra));
    return v;
}

#define CLUSTER_BAR()                                                       \
    do {                                                                    \
        asm volatile("barrier.cluster.arrive.aligned;" ::: "memory");       \
        asm volatile("barrier.cluster.wait.aligned;"   ::: "memory");       \
    } while (0)

__global__ void __launch_bounds__(NTHR, 1) __cluster_dims__(NSTRIP, 1, 1)
cml_ds_kernel(const float* __restrict__ drive,
              const float* __restrict__ Klocal,
              float* __restrict__ out)
{
    extern __shared__ float sm[];
    float* MB0 = sm;
    float* MB1 = sm + BUF;
    float* DS  = sm + DS_OFF;              // 64 rows of beta*drive

    const int tx = threadIdx.x;
    const int ty = threadIdx.y;
    const int strip = blockIdx.x;          // cluster rank 0..3
    const int c     = blockIdx.y;
    const int b     = blockIdx.z;
    const int x4    = tx * 4;
    const int x0    = tx * 8;
    const int rbase = strip * RCTA;

    // Folded kernel K' = R*(1-BETA)*(EPS*K + (1-EPS)*delta)
    float kk[3][3];
    {
        const float* kc = Klocal + c * 9;
        #pragma unroll
        for (int j = 0; j < 3; ++j)
            #pragma unroll
            for (int i = 0; i < 3; ++i) {
                float v = EPS_P * kc[j * 3 + i];
                if (j == 1 && i == 1) v += (1.0f - EPS_P);
                kk[j][i] = R_PARAM * (1.0f - BETA_P) * v;
            }
    }

    const long long plane = (long long)(b * 8 + c) * NPLANE;
    const float* dpl = drive + plane;

    // Pair assignment (as r7): pair A interior first, pair B holds the
    // cross-CTA boundary rows (ty==0 -> rows 0,1 ; ty==15 -> rows 62,63).
    const int pA = (ty == 0) ? 16 : ty;          // 1..16
    const int pB = (ty == 0) ? 0  : ty + 16;     // 0, 17..31
    const int A0 = 2 * pA - 1, A1 = 2 * pA, A2 = 2 * pA + 1, A3 = 2 * pA + 2;
    const int B0 = (pB == 0)  ? 64 : 2 * pB - 1;
    const int B1 = 2 * pB,     B2 = 2 * pB + 1;
    const int B3 = (pB == 31) ? 65 : 2 * pB + 2;
    const int irA = rbase + 2 * pA;
    const int irB = rbase + 2 * pB;

    // ---- init: MB0 rows 0..63 <- mapped(drive); DS rows <- beta*drive ----
    #pragma unroll
    for (int k = 0; k < 4; ++k) {
        int r = ty + TYN * k;                   // 0..63
        const float* dr = dpl + (long long)(rbase + r) * W + x0;
        float4 dA = *reinterpret_cast<const float4*>(dr);
        float4 dB = *reinterpret_cast<const float4*>(dr + 4);

        float4 mA, mB;
        mA.x = fmaf(-dA.x, dA.x, dA.x);  mA.y = fmaf(-dA.y, dA.y, dA.y);
        mA.z = fmaf(-dA.z, dA.z, dA.z);  mA.w = fmaf(-dA.w, dA.w, dA.w);
        mB.x = fmaf(-dB.x, dB.x, dB.x);  mB.y = fmaf(-dB.y, dB.y, dB.y);
        mB.z = fmaf(-dB.z, dB.z, dB.z);  mB.w = fmaf(-dB.w, dB.w, dB.w);
        float* p0 = MB0 + r * W;
        *reinterpret_cast<float4*>(p0 + x4)       = mA;
        *reinterpret_cast<float4*>(p0 + 128 + x4) = mB;

        float4 bA = make_float4(BETA_P * dA.x, BETA_P * dA.y,
                                BETA_P * dA.z, BETA_P * dA.w);
        float4 bB = make_float4(BETA_P * dB.x, BETA_P * dB.y,
                                BETA_P * dB.z, BETA_P * dB.w);
        float* pd = DS + r * W;
        *reinterpret_cast<float4*>(pd + x4)       = bA;
        *reinterpret_cast<float4*>(pd + 128 + x4) = bB;
    }
    CLUSTER_BAR();

    // stats: pair slots A and B. [rowInPair*8 + i]
    float sumA[16], ssqA[16], sumB[16], ssqB[16];
    #pragma unroll
    for (int i = 0; i < 16; ++i) {
        sumA[i] = 0.f; ssqA[i] = 0.f; sumB[i] = 0.f; ssqB[i] = 0.f;
    }

    #define ACCROW(acc, cc)                                                    \
        {                                                                      \
            float c0 = (cc)[0], c1 = (cc)[1], c2 = (cc)[2];                    \
            acc[0] = fmaf(c0, lm, fmaf(c1, m0, fmaf(c2, m1, acc[0])));         \
            acc[1] = fmaf(c0, m0, fmaf(c1, m1, fmaf(c2, m2, acc[1])));         \
            acc[2] = fmaf(c0, m1, fmaf(c1, m2, fmaf(c2, m3, acc[2])));         \
            acc[3] = fmaf(c0, m2, fmaf(c1, m3, fmaf(c2, m4, acc[3])));         \
            acc[4] = fmaf(c0, m3, fmaf(c1, m4, fmaf(c2, m5, acc[4])));         \
            acc[5] = fmaf(c0, m4, fmaf(c1, m5, fmaf(c2, m6, acc[5])));         \
            acc[6] = fmaf(c0, m5, fmaf(c1, m6, fmaf(c2, m7, acc[6])));         \
            acc[7] = fmaf(c0, m6, fmaf(c1, m7, fmaf(c2, rm, acc[7])));         \
        }

    #define PAIR_CONV(Min, R0, R1, R2, R3, acc0, acc1)                         \
        {                                                                      \
            const int rows_[4] = { (R0), (R1), (R2), (R3) };                   \
            _Pragma("unroll")                                                  \
            for (int jr = 0; jr < 4; ++jr) {                                   \
                const float* rp = (Min) + rows_[jr] * W;                       \
                float4 qa = *reinterpret_cast<const float4*>(rp + x4);         \
                float4 qb = *reinterpret_cast<const float4*>(rp + 128 + x4);   \
                float m0 = qa.x, m1 = qa.y, m2 = qa.z, m3 = qa.w;              \
                float m4 = qb.x, m5 = qb.y, m6 = qb.z, m7 = qb.w;              \
                float lm = __shfl_up_sync(0xffffffffu, m7, 1);                 \
                float rm = __shfl_down_sync(0xffffffffu, m0, 1);               \
                if (tx == 0)  lm = 0.f;                                        \
                if (tx == 31) rm = 0.f;                                        \
                if (jr < 3) ACCROW(acc0, kk[jr])                               \
                if (jr > 0) ACCROW(acc1, kk[jr - 1])                           \
            }                                                                  \
        }

    // acc <- DS row (beta*drive), via cheap LDS instead of LDG
    #define LOAD_DS_ACC(rr, acc)                                               \
        {                                                                      \
            const float* pd = DS + (rr) * W;                                   \
            float4 aA = *reinterpret_cast<const float4*>(pd + x4);             \
            float4 aB = *reinterpret_cast<const float4*>(pd + 128 + x4);       \
            acc[0] = aA.x;  acc[1] = aA.y;  acc[2] = aA.z;  acc[3] = aA.w;     \
            acc[4] = aB.x;  acc[5] = aB.y;  acc[6] = aB.z;  acc[7] = aB.w;     \
        }

    // halo pull into local slots of Min; fetching warp is sole reader.
    #define HALO_PROLOGUE(Min)                                                 \
        {                                                                      \
            if (ty == 0) {                                                     \
                float4 h0 = make_float4(0.f, 0.f, 0.f, 0.f), h1 = h0;          \
                if (strip > 0) {                                               \
                    uint32_t a = smem_u32((Min) + 63 * W + x4);                \
                    h0 = dsmem_ld4(a,       (uint32_t)(strip - 1));            \
                    h1 = dsmem_ld4(a + 512, (uint32_t)(strip - 1));            \
                }                                                              \
                *reinterpret_cast<float4*>((Min) + 64 * W + x4)       = h0;    \
                *reinterpret_cast<float4*>((Min) + 64 * W + 128 + x4) = h1;    \
            } else if (ty == TYN - 1) {                                        \
                float4 h0 = make_float4(0.f, 0.f, 0.f, 0.f), h1 = h0;          \
                if (strip < NSTRIP - 1) {                                      \
                    uint32_t a = smem_u32((Min) + x4);                         \
                    h0 = dsmem_ld4(a,       (uint32_t)(strip + 1));            \
                    h1 = dsmem_ld4(a + 512, (uint32_t)(strip + 1));            \
                }                                                              \
                *reinterpret_cast<float4*>((Min) + 65 * W + x4)       = h0;    \
                *reinterpret_cast<float4*>((Min) + 65 * W + 128 + x4) = h1;    \
            }                                                                  \
        }

    // one pair: acc init from DS, conv, clamp, stats, map, store
    #define PAIR_STEP(Min, Mout, R0, R1, R2, R3, orow, sumP, ssqP)             \
        {                                                                      \
            float acc0[8], acc1[8];                                            \
            LOAD_DS_ACC((orow), acc0)                                          \
            LOAD_DS_ACC((orow) + 1, acc1)                                      \
            PAIR_CONV(Min, R0, R1, R2, R3, acc0, acc1)                         \
            _Pragma("unroll")                                                  \
            for (int i = 0; i < 8; ++i) {                                      \
                float g = clampg(acc0[i]);                                     \
                sumP[i] += g;  ssqP[i] = fmaf(g, g, ssqP[i]);                  \
                acc0[i] = fmaf(-g, g, g);                                      \
            }                                                                  \
            _Pragma("unroll")                                                  \
            for (int i = 0; i < 8; ++i) {                                      \
                float g = clampg(acc1[i]);                                     \
                sumP[i + 8] += g;  ssqP[i + 8] = fmaf(g, g, ssqP[i + 8]);      \
                acc1[i] = fmaf(-g, g, g);                                      \
            }                                                                  \
            float* op0 = (Mout) + (orow) * W;                                  \
            float* op1 = (Mout) + ((orow) + 1) * W;                            \
            *reinterpret_cast<float4*>(op0 + x4)       = make_float4(acc0[0], acc0[1], acc0[2], acc0[3]); \
            *reinterpret_cast<float4*>(op0 + 128 + x4) = make_float4(acc0[4], acc0[5], acc0[6], acc0[7]); \
            *reinterpret_cast<float4*>(op1 + x4)       = make_float4(acc1[0], acc1[1], acc1[2], acc1[3]); \
            *reinterpret_cast<float4*>(op1 + 128 + x4) = make_float4(acc1[4], acc1[5], acc1[6], acc1[7]); \
        }

    // ---- steps 0..13: halo pull -> pair A -> pair B -> cluster barrier ----
    #pragma unroll 1
    for (int t = 0; t < NSTEPS - 1; ++t) {
        float* Min  = (t & 1) ? MB1 : MB0;
        float* Mout = (t & 1) ? MB0 : MB1;

        HALO_PROLOGUE(Min)
        PAIR_STEP(Min, Mout, A0, A1, A2, A3, 2 * pA, sumA, ssqA)   // interior
        PAIR_STEP(Min, Mout, B0, B1, B2, B3, 2 * pB, sumB, ssqB)   // boundary
        CLUSTER_BAR();
    }

    // ---- final step t=14 (reads MB0): compute pairs, write 5 outputs ----
    {
        float* Min = MB0;
        const float inv = 1.0f / (float)NSTEPS;

        HALO_PROLOGUE(Min)

        #pragma unroll
        for (int pp = 0; pp < 2; ++pp) {
            const int irr  = pp ? irB : irA;
            float* sumP = pp ? sumB : sumA;
            float* ssqP = pp ? ssqB : ssqA;

            float acc0[8] = {0.f,0.f,0.f,0.f,0.f,0.f,0.f,0.f};
            float acc1[8] = {0.f,0.f,0.f,0.f,0.f,0.f,0.f,0.f};
            if (pp == 0) { PAIR_CONV(Min, A0, A1, A2, A3, acc0, acc1) }
            else         { PAIR_CONV(Min, B0, B1, B2, B3, acc0, acc1) }

            #pragma unroll
            for (int half = 0; half < 2; ++half) {
                float* acc = half ? acc1 : acc0;
                const int off = half * 8;
                const int ir  = irr + half;
                long long idx = plane + (long long)ir * W + x0;

                // raw drive from global (needed exactly for delta)
                const float* dr = dpl + (long long)ir * W + x0;
                float4 dA = *reinterpret_cast<const float4*>(dr);
                float4 dB = *reinterpret_cast<const float4*>(dr + 4);
                float dv[8] = { dA.x, dA.y, dA.z, dA.w, dB.x, dB.y, dB.z, dB.w };

                float g[8], mean[8], var[8], del[8];
                #pragma unroll
                for (int i = 0; i < 8; ++i) {
                    g[i] = clampg(fmaf(BETA_P, dv[i], acc[i]));
                    float s  = sumP[off + i] + g[i];
                    float sq = fmaf(g[i], g[i], ssqP[off + i]);
                    mean[i] = s * inv;
                    var[i]  = fmaf(-mean[i], mean[i], sq * inv);
                    del[i]  = g[i] - dv[i];
                }
                *reinterpret_cast<float4*>(out + idx)                = make_float4(g[0], g[1], g[2], g[3]);
                *reinterpret_cast<float4*>(out + idx + 4)            = make_float4(g[4], g[5], g[6], g[7]);
                *reinterpret_cast<float4*>(out + NTOT + idx)         = make_float4(mean[0], mean[1], mean[2], mean[3]);
                *reinterpret_cast<float4*>(out + NTOT + idx + 4)     = make_float4(mean[4], mean[5], mean[6], mean[7]);
                *reinterpret_cast<float4*>(out + 2 * NTOT + idx)     = make_float4(var[0], var[1], var[2], var[3]);
                *reinterpret_cast<float4*>(out + 2 * NTOT + idx + 4) = make_float4(var[4], var[5], var[6], var[7]);
                *reinterpret_cast<float4*>(out + 3 * NTOT + idx)     = make_float4(del[0], del[1], del[2], del[3]);
                *reinterpret_cast<float4*>(out + 3 * NTOT + idx + 4) = make_float4(del[4], del[5], del[6], del[7]);
                *reinterpret_cast<float4*>(out + 4 * NTOT + idx)     = make_float4(del[0], del[1], del[2], del[3]);
                *reinterpret_cast<float4*>(out + 4 * NTOT + idx + 4) = make_float4(del[4], del[5], del[6], del[7]);
            }
        }
    }

    // no CTA may exit while a neighbor might still read its smem
    CLUSTER_BAR();
}

extern "C" void kernel_launch(void* const* d_in, const int* in_sizes, int n_in,
                              void* d_out, int out_size)
{
    const float* drive  = (const float*)d_in[0];   // [16,8,256,256] f32
    const float* Klocal = (const float*)d_in[1];   // [8,1,3,3] f32
    float* out = (float*)d_out;                    // 5 x [16,8,256,256] f32

    cudaFuncSetAttribute(cml_ds_kernel,
                         cudaFuncAttributeMaxDynamicSharedMemorySize, SMEM_BYTES);

    dim3 grid(NSTRIP, 8, 16);          // 4 strips (1 cluster/plane) x 8 ch x 16 b
    dim3 block(TXN, TYN);              // 512 threads
    cml_ds_kernel<<<grid, block, SMEM_BYTES>>>(drive, Klocal, out);
}

// round 15
// speedup vs baseline: 1.4967x; 1.0406x over previous
#include <cuda_runtime.h>
#include <cstdint>

// ---------------------------------------------------------------------------
// CML2DWithStats, round 15: r14 base (cluster-4, DSMEM halo, DS = beta*drive
// smem tile) + SPLIT cluster barrier with late-halo boundary pair.
//
//   g_{t+1} = clamp( conv3x3( m_t, K' ) + BETA*drive ),  m = g*(1-g)
//   K' = R*(1-BETA)*(EPS*K + (1-EPS)*delta_center)
//
// Cluster (4,1,1) per plane; rank = 64-row strip. Per-CTA smem:
//   MB0/MB1: two 66-row mapped buffers (rows 0..63 own, 64/65 halo slots)
//   DS:      64-row beta*drive tile (filled once at init)
// Per step:
//   1. halo pull into local slots of Min (warps ty 0/15, sole readers)
//   2. pair B (boundary; conv row order B1,B2,B0,B3 so the halo slot is
//      consumed LAST -> DSMEM latency hidden behind ~2/3 of the pair)
//   3. cluster.arrive  (boundary rows 0,1,62,63 of Mout now released)
//   4. pair A (interior) -- hides the barrier propagation
//   5. __syncthreads (intra-CTA ordering of Mout)  6. cluster.wait (~free)
// ---------------------------------------------------------------------------

#define R_PARAM  3.9f
#define EPS_P    0.3f
#define BETA_P   0.15f
#define NSTEPS   15
#define CLAMP_LO 1e-4f
#define CLAMP_HI (1.0f - 1e-4f)

constexpr int W      = 256;
constexpr int RCTA   = 64;
constexpr int NSTRIP = 4;
constexpr int BROWS  = 66;                 // 64 own + 2 halo slots
constexpr int TXN    = 32;
constexpr int TYN    = 16;
constexpr int NTHR   = TXN * TYN;          // 512
constexpr int NPLANE = W * 256;
constexpr long long NTOT = 16LL * 8 * NPLANE;
constexpr int BUF        = BROWS * W;                  // 16896 floats
constexpr int DS_OFF     = 2 * BUF;                    // DS tile offset (floats)
constexpr int SMEM_BYTES = (2 * BUF + RCTA * W) * 4;   // 200704 B

__device__ __forceinline__ float clampg(float v) {
    return fminf(fmaxf(v, CLAMP_LO), CLAMP_HI);
}

__device__ __forceinline__ uint32_t smem_u32(const void* p) {
    uint32_t a;
    asm("{ .reg .u64 t; cvta.to.shared.u64 t, %1; cvt.u32.u64 %0, t; }"
        : "=r"(a) : "l"(p));
    return a;
}

__device__ __forceinline__ float4 dsmem_ld4(uint32_t my_addr, uint32_t rank) {
    uint32_t ra; float4 v;
    asm volatile("mapa.shared::cluster.u32 %0, %1, %2;"
                 : "=r"(ra) : "r"(my_addr), "r"(rank));
    asm volatile("ld.shared::cluster.v4.f32 {%0, %1, %2, %3}, [%4];"
                 : "=f"(v.x), "=f"(v.y), "=f"(v.z), "=f"(v.w) : "r"(ra));
    return v;
}

#define CLUSTER_ARRIVE() \
    asm volatile("barrier.cluster.arrive.aligned;" ::: "memory")
#define CLUSTER_WAIT() \
    asm volatile("barrier.cluster.wait.aligned;"   ::: "memory")
#define CLUSTER_BAR()  do { CLUSTER_ARRIVE(); CLUSTER_WAIT(); } while (0)

__global__ void __launch_bounds__(NTHR, 1) __cluster_dims__(NSTRIP, 1, 1)
cml_ds_split_kernel(const float* __restrict__ drive,
                    const float* __restrict__ Klocal,
                    float* __restrict__ out)
{
    extern __shared__ float sm[];
    float* MB0 = sm;
    float* MB1 = sm + BUF;
    float* DS  = sm + DS_OFF;              // 64 rows of beta*drive

    const int tx = threadIdx.x;
    const int ty = threadIdx.y;
    const int strip = blockIdx.x;          // cluster rank 0..3
    const int c     = blockIdx.y;
    const int b     = blockIdx.z;
    const int x4    = tx * 4;
    const int x0    = tx * 8;
    const int rbase = strip * RCTA;

    // Folded kernel K' = R*(1-BETA)*(EPS*K + (1-EPS)*delta)
    float kk[3][3];
    {
        const float* kc = Klocal + c * 9;
        #pragma unroll
        for (int j = 0; j < 3; ++j)
            #pragma unroll
            for (int i = 0; i < 3; ++i) {
                float v = EPS_P * kc[j * 3 + i];
                if (j == 1 && i == 1) v += (1.0f - EPS_P);
                kk[j][i] = R_PARAM * (1.0f - BETA_P) * v;
            }
    }

    const long long plane = (long long)(b * 8 + c) * NPLANE;
    const float* dpl = drive + plane;

    // Pair assignment: pair B holds the cross-CTA boundary rows
    //   ty==0  -> pB = 0  (rows 0,1; B0 = halo slot 64)
    //   ty==15 -> pB = 31 (rows 62,63; B3 = halo slot 65)
    const int pA = (ty == 0) ? 16 : ty;          // 1..16
    const int pB = (ty == 0) ? 0  : ty + 16;     // 0, 17..31
    const int A0 = 2 * pA - 1, A1 = 2 * pA, A2 = 2 * pA + 1, A3 = 2 * pA + 2;
    const int B0 = (pB == 0)  ? 64 : 2 * pB - 1;
    const int B1 = 2 * pB,     B2 = 2 * pB + 1;
    const int B3 = (pB == 31) ? 65 : 2 * pB + 2;
    const int irA = rbase + 2 * pA;
    const int irB = rbase + 2 * pB;

    // ---- init: MB0 rows 0..63 <- mapped(drive); DS rows <- beta*drive ----
    #pragma unroll
    for (int k = 0; k < 4; ++k) {
        int r = ty + TYN * k;                   // 0..63
        const float* dr = dpl + (long long)(rbase + r) * W + x0;
        float4 dA = *reinterpret_cast<const float4*>(dr);
        float4 dB = *reinterpret_cast<const float4*>(dr + 4);

        float4 mA, mB;
        mA.x = fmaf(-dA.x, dA.x, dA.x);  mA.y = fmaf(-dA.y, dA.y, dA.y);
        mA.z = fmaf(-dA.z, dA.z, dA.z);  mA.w = fmaf(-dA.w, dA.w, dA.w);
        mB.x = fmaf(-dB.x, dB.x, dB.x);  mB.y = fmaf(-dB.y, dB.y, dB.y);
        mB.z = fmaf(-dB.z, dB.z, dB.z);  mB.w = fmaf(-dB.w, dB.w, dB.w);
        float* p0 = MB0 + r * W;
        *reinterpret_cast<float4*>(p0 + x4)       = mA;
        *reinterpret_cast<float4*>(p0 + 128 + x4) = mB;

        float4 bA = make_float4(BETA_P * dA.x, BETA_P * dA.y,
                                BETA_P * dA.z, BETA_P * dA.w);
        float4 bB = make_float4(BETA_P * dB.x, BETA_P * dB.y,
                                BETA_P * dB.z, BETA_P * dB.w);
        float* pd = DS + r * W;
        *reinterpret_cast<float4*>(pd + x4)       = bA;
        *reinterpret_cast<float4*>(pd + 128 + x4) = bB;
    }
    CLUSTER_BAR();

    // stats: pair slots A and B. [rowInPair*8 + i]
    float sumA[16], ssqA[16], sumB[16], ssqB[16];
    #pragma unroll
    for (int i = 0; i < 16; ++i) {
        sumA[i] = 0.f; ssqA[i] = 0.f; sumB[i] = 0.f; ssqB[i] = 0.f;
    }

    #define ACCROW(acc, cc)                                                    \
        {                                                                      \
            float c0 = (cc)[0], c1 = (cc)[1], c2 = (cc)[2];                    \
            acc[0] = fmaf(c0, lm, fmaf(c1, m0, fmaf(c2, m1, acc[0])));         \
            acc[1] = fmaf(c0, m0, fmaf(c1, m1, fmaf(c2, m2, acc[1])));         \
            acc[2] = fmaf(c0, m1, fmaf(c1, m2, fmaf(c2, m3, acc[2])));         \
            acc[3] = fmaf(c0, m2, fmaf(c1, m3, fmaf(c2, m4, acc[3])));         \
            acc[4] = fmaf(c0, m3, fmaf(c1, m4, fmaf(c2, m5, acc[4])));         \
            acc[5] = fmaf(c0, m4, fmaf(c1, m5, fmaf(c2, m6, acc[5])));         \
            acc[6] = fmaf(c0, m5, fmaf(c1, m6, fmaf(c2, m7, acc[6])));         \
            acc[7] = fmaf(c0, m6, fmaf(c1, m7, fmaf(c2, rm, acc[7])));         \
        }

    #define LOAD_MROW(Min, slot)                                               \
        const float* rp = (Min) + (slot) * W;                                  \
        float4 qa = *reinterpret_cast<const float4*>(rp + x4);                 \
        float4 qb = *reinterpret_cast<const float4*>(rp + 128 + x4);           \
        float m0 = qa.x, m1 = qa.y, m2 = qa.z, m3 = qa.w;                      \
        float m4 = qb.x, m5 = qb.y, m6 = qb.z, m7 = qb.w;                      \
        float lm = __shfl_up_sync(0xffffffffu, m7, 1);                         \
        float rm = __shfl_down_sync(0xffffffffu, m0, 1);                       \
        if (tx == 0)  lm = 0.f;                                                \
        if (tx == 31) rm = 0.f;

    // normal pair conv: rows R0,R1,R2,R3 in order
    #define PAIR_CONV(Min, R0, R1, R2, R3, acc0, acc1)                         \
        {                                                                      \
            { LOAD_MROW(Min, R0)  ACCROW(acc0, kk[0]) }                        \
            { LOAD_MROW(Min, R1)  ACCROW(acc0, kk[1]) ACCROW(acc1, kk[0]) }    \
            { LOAD_MROW(Min, R2)  ACCROW(acc0, kk[2]) ACCROW(acc1, kk[1]) }    \
            { LOAD_MROW(Min, R3)  ACCROW(acc1, kk[2]) }                        \
        }

    // boundary pair conv: order B1,B2,B0,B3 so halo slots (B0 for ty0,
    // B3 for ty15) are consumed late -> DSMEM+STS->LDS chain hidden.
    #define PAIR_CONV_B(Min, acc0, acc1)                                       \
        {                                                                      \
            { LOAD_MROW(Min, B1)  ACCROW(acc0, kk[1]) ACCROW(acc1, kk[0]) }    \
            { LOAD_MROW(Min, B2)  ACCROW(acc0, kk[2]) ACCROW(acc1, kk[1]) }    \
            { LOAD_MROW(Min, B0)  ACCROW(acc0, kk[0]) }                        \
            { LOAD_MROW(Min, B3)  ACCROW(acc1, kk[2]) }                        \
        }

    // acc <- DS row (beta*drive) via LDS
    #define LOAD_DS_ACC(rr, acc)                                               \
        {                                                                      \
            const float* pd = DS + (rr) * W;                                   \
            float4 aA = *reinterpret_cast<const float4*>(pd + x4);             \
            float4 aB = *reinterpret_cast<const float4*>(pd + 128 + x4);       \
            acc[0] = aA.x;  acc[1] = aA.y;  acc[2] = aA.z;  acc[3] = aA.w;     \
            acc[4] = aB.x;  acc[5] = aB.y;  acc[6] = aB.z;  acc[7] = aB.w;     \
        }

    // halo pull into local slots of Min; fetching warp is sole reader.
    #define HALO_PROLOGUE(Min)                                                 \
        {                                                                      \
            if (ty == 0) {                                                     \
                float4 h0 = make_float4(0.f, 0.f, 0.f, 0.f), h1 = h0;          \
                if (strip > 0) {                                               \
                    uint32_t a = smem_u32((Min) + 63 * W + x4);                \
                    h0 = dsmem_ld4(a,       (uint32_t)(strip - 1));            \
                    h1 = dsmem_ld4(a + 512, (uint32_t)(strip - 1));            \
                }                                                              \
                *reinterpret_cast<float4*>((Min) + 64 * W + x4)       = h0;    \
                *reinterpret_cast<float4*>((Min) + 64 * W + 128 + x4) = h1;    \
            } else if (ty == TYN - 1) {                                        \
                float4 h0 = make_float4(0.f, 0.f, 0.f, 0.f), h1 = h0;          \
                if (strip < NSTRIP - 1) {                                      \
                    uint32_t a = smem_u32((Min) + x4);                         \
                    h0 = dsmem_ld4(a,       (uint32_t)(strip + 1));            \
                    h1 = dsmem_ld4(a + 512, (uint32_t)(strip + 1));            \
                }                                                              \
                *reinterpret_cast<float4*>((Min) + 65 * W + x4)       = h0;    \
                *reinterpret_cast<float4*>((Min) + 65 * W + 128 + x4) = h1;    \
            }                                                                  \
        }

    // epilogue shared by both pairs: clamp, stats, map, store
    #define PAIR_EPILOG(Mout, orow, acc0, acc1, sumP, ssqP)                    \
        {                                                                      \
            _Pragma("unroll")                                                  \
            for (int i = 0; i < 8; ++i) {                                      \
                float g = clampg(acc0[i]);                                     \
                sumP[i] += g;  ssqP[i] = fmaf(g, g, ssqP[i]);                  \
                acc0[i] = fmaf(-g, g, g);                                      \
            }                                                                  \
            _Pragma("unroll")                                                  \
            for (int i = 0; i < 8; ++i) {                                      \
                float g = clampg(acc1[i]);                                     \
                sumP[i + 8] += g;  ssqP[i + 8] = fmaf(g, g, ssqP[i + 8]);      \
                acc1[i] = fmaf(-g, g, g);                                      \
            }                                                                  \
            float* op0 = (Mout) + (orow) * W;                                  \
            float* op1 = (Mout) + ((orow) + 1) * W;                            \
            *reinterpret_cast<float4*>(op0 + x4)       = make_float4(acc0[0], acc0[1], acc0[2], acc0[3]); \
            *reinterpret_cast<float4*>(op0 + 128 + x4) = make_float4(acc0[4], acc0[5], acc0[6], acc0[7]); \
            *reinterpret_cast<float4*>(op1 + x4)       = make_float4(acc1[0], acc1[1], acc1[2], acc1[3]); \
            *reinterpret_cast<float4*>(op1 + 128 + x4) = make_float4(acc1[4], acc1[5], acc1[6], acc1[7]); \
        }

    // ---- steps 0..13: halo -> pair B -> arrive -> pair A -> sync -> wait ----
    #pragma unroll 1
    for (int t = 0; t < NSTEPS - 1; ++t) {
        float* Min  = (t & 1) ? MB1 : MB0;
        float* Mout = (t & 1) ? MB0 : MB1;

        HALO_PROLOGUE(Min)

        {   // pair B (boundary rows) with late-halo conv order
            float acc0[8], acc1[8];
            LOAD_DS_ACC(2 * pB, acc0)
            LOAD_DS_ACC(2 * pB + 1, acc1)
            PAIR_CONV_B(Min, acc0, acc1)
            PAIR_EPILOG(Mout, 2 * pB, acc0, acc1, sumB, ssqB)
        }
        CLUSTER_ARRIVE();                  // releases boundary rows 0,1,62,63

        {   // pair A (interior) hides the barrier propagation
            float acc0[8], acc1[8];
            LOAD_DS_ACC(2 * pA, acc0)
            LOAD_DS_ACC(2 * pA + 1, acc1)
            PAIR_CONV(Min, A0, A1, A2, A3, acc0, acc1)
            PAIR_EPILOG(Mout, 2 * pA, acc0, acc1, sumA, ssqA)
        }
        __syncthreads();                   // intra-CTA ordering of Mout
        CLUSTER_WAIT();                    // ~free by now
    }

    // ---- final step t=14 (reads MB0): compute pairs, write 5 outputs ----
    {
        float* Min = MB0;
        const float inv = 1.0f / (float)NSTEPS;

        HALO_PROLOGUE(Min)

        #pragma unroll
        for (int pp = 0; pp < 2; ++pp) {
            const int irr  = pp ? irB : irA;
            float* sumP = pp ? sumB : sumA;
            float* ssqP = pp ? ssqB : ssqA;

            float acc0[8] = {0.f,0.f,0.f,0.f,0.f,0.f,0.f,0.f};
            float acc1[8] = {0.f,0.f,0.f,0.f,0.f,0.f,0.f,0.f};
            if (pp == 0) { PAIR_CONV(Min, A0, A1, A2, A3, acc0, acc1) }
            else         { PAIR_CONV_B(Min, acc0, acc1) }

            #pragma unroll
            for (int half = 0; half < 2; ++half) {
                float* acc = half ? acc1 : acc0;
                const int off = half * 8;
                const int ir  = irr + half;
                long long idx = plane + (long long)ir * W + x0;

                // raw drive from global (needed exactly for delta)
                const float* dr = dpl + (long long)ir * W + x0;
                float4 dA = *reinterpret_cast<const float4*>(dr);
                float4 dB = *reinterpret_cast<const float4*>(dr + 4);
                float dv[8] = { dA.x, dA.y, dA.z, dA.w, dB.x, dB.y, dB.z, dB.w };

                float g[8], mean[8], var[8], del[8];
                #pragma unroll
                for (int i = 0; i < 8; ++i) {
                    g[i] = clampg(fmaf(BETA_P, dv[i], acc[i]));
                    float s  = sumP[off + i] + g[i];
                    float sq = fmaf(g[i], g[i], ssqP[off + i]);
                    mean[i] = s * inv;
                    var[i]  = fmaf(-mean[i], mean[i], sq * inv);
                    del[i]  = g[i] - dv[i];
                }
                *reinterpret_cast<float4*>(out + idx)                = make_float4(g[0], g[1], g[2], g[3]);
                *reinterpret_cast<float4*>(out + idx + 4)            = make_float4(g[4], g[5], g[6], g[7]);
                *reinterpret_cast<float4*>(out + NTOT + idx)         = make_float4(mean[0], mean[1], mean[2], mean[3]);
                *reinterpret_cast<float4*>(out + NTOT + idx + 4)     = make_float4(mean[4], mean[5], mean[6], mean[7]);
                *reinterpret_cast<float4*>(out + 2 * NTOT + idx)     = make_float4(var[0], var[1], var[2], var[3]);
                *reinterpret_cast<float4*>(out + 2 * NTOT + idx + 4) = make_float4(var[4], var[5], var[6], var[7]);
                *reinterpret_cast<float4*>(out + 3 * NTOT + idx)     = make_float4(del[0], del[1], del[2], del[3]);
                *reinterpret_cast<float4*>(out + 3 * NTOT + idx + 4) = make_float4(del[4], del[5], del[6], del[7]);
                *reinterpret_cast<float4*>(out + 4 * NTOT + idx)     = make_float4(del[0], del[1], del[2], del[3]);
                *reinterpret_cast<float4*>(out + 4 * NTOT + idx + 4) = make_float4(del[4], del[5], del[6], del[7]);
            }
        }
    }

    // no CTA may exit while a neighbor might still read its smem
    CLUSTER_BAR();
}

extern "C" void kernel_launch(void* const* d_in, const int* in_sizes, int n_in,
                              void* d_out, int out_size)
{
    const float* drive  = (const float*)d_in[0];   // [16,8,256,256] f32
    const float* Klocal = (const float*)d_in[1];   // [8,1,3,3] f32
    float* out = (float*)d_out;                    // 5 x [16,8,256,256] f32

    cudaFuncSetAttribute(cml_ds_split_kernel,
                         cudaFuncAttributeMaxDynamicSharedMemorySize, SMEM_BYTES);

    dim3 grid(NSTRIP, 8, 16);          // 4 strips (1 cluster/plane) x 8 ch x 16 b
    dim3 block(TXN, TYN);              // 512 threads
    cml_ds_split_kernel<<<grid, block, SMEM_BYTES>>>(drive, Klocal, out);
}